// round 14
// baseline (speedup 1.0000x reference)
#include <cuda_runtime.h>
#include <cstdint>

#define N_NODES 40000
#define N_EDGES 640000
#define IN_CH   128
#define OUT_CH  128
#define NUM_RBF 64
#define TILE64  64
#define NT64    (N_EDGES / TILE64)     // 10000

// ---------------- device scratch (no allocs allowed) ----------------
__device__ float g_h[(size_t)N_NODES * OUT_CH];      // x @ Wl + bl

// ---------------- helpers ----------------
__device__ __forceinline__ float rnd_tf32(float x) {
    float r;
    asm("cvt.rna.tf32.f32 %0, %1;" : "=f"(r) : "f"(x));
    return r;
}
__device__ __forceinline__ uint32_t tf32_bits(float x) {
    return __float_as_uint(rnd_tf32(x));
}
__device__ __forceinline__ uint32_t smem_u32(const void* p) {
    uint32_t a;
    asm("{ .reg .u64 t; cvta.to.shared.u64 t, %1; cvt.u32.u64 %0, t; }"
        : "=r"(a) : "l"(p));
    return a;
}
__device__ __forceinline__ void red_add_v4(float* addr, float4 v) {
    asm volatile("red.global.add.v4.f32 [%0], {%1,%2,%3,%4};"
                 :: "l"(addr), "f"(v.x), "f"(v.y), "f"(v.z), "f"(v.w) : "memory");
}
__device__ __forceinline__ void cp16(uint32_t saddr, const void* g) {
    asm volatile("cp.async.cg.shared.global [%0], [%1], 16;"
                 :: "r"(saddr), "l"(g) : "memory");
}
__device__ __forceinline__ void cp_commit() {
    asm volatile("cp.async.commit_group;" ::: "memory");
}
__device__ __forceinline__ void cp_wait0() {
    asm volatile("cp.async.wait_group 0;" ::: "memory");
}
__device__ __forceinline__ void bar_compute() {       // warps 0-7 only
    asm volatile("bar.sync 1, 256;" ::: "memory");
}
// mma.sync m16n8k8 tf32 (baseline PTX, sm_80+)
__device__ __forceinline__ void mma_tf32(float d[4], const uint32_t a[4],
                                         uint32_t b0, uint32_t b1) {
    asm volatile(
        "mma.sync.aligned.m16n8k8.row.col.f32.tf32.tf32.f32 "
        "{%0,%1,%2,%3}, {%4,%5,%6,%7}, {%8,%9}, {%0,%1,%2,%3};"
        : "+f"(d[0]), "+f"(d[1]), "+f"(d[2]), "+f"(d[3])
        : "r"(a[0]), "r"(a[1]), "r"(a[2]), "r"(a[3]), "r"(b0), "r"(b1));
}
__device__ __forceinline__ void ldsm_x4(uint32_t a[4], uint32_t saddr) {
    asm volatile("ldmatrix.sync.aligned.m8n8.x4.shared.b16 {%0,%1,%2,%3}, [%4];"
                 : "=r"(a[0]), "=r"(a[1]), "=r"(a[2]), "=r"(a[3]) : "r"(saddr));
}

// ---------------------------------------------------------------------------
// node linear: h = x @ Wl + bl via tf32 mma (unchanged, proven)
// ---------------------------------------------------------------------------
#define NL_LDX 132
#define NL_SMEM_BYTES (128 * NL_LDX * 4)

__global__ void __launch_bounds__(256)
node_linear_mma(const float* __restrict__ x, const float* __restrict__ Wl,
                const float* __restrict__ bl, float* __restrict__ h) {
    extern __shared__ float s_x[];
    const int tid = threadIdx.x;
    const int wid = tid >> 5, lane = tid & 31;
    const int qr = lane >> 2, tig = lane & 3;
    const int nb = wid * 16;
    const int m0 = blockIdx.x * 128;
    const uint32_t sx_u32 = smem_u32(s_x);
    const uint32_t a_off = ((lane & 15) * NL_LDX + ((lane >> 4) << 2)) * 4u;

    uint32_t wf[16][2][2];
#pragma unroll
    for (int ks = 0; ks < 16; ks++)
#pragma unroll
        for (int nt = 0; nt < 2; nt++) {
            int n = nb + nt * 8 + qr;
            wf[ks][nt][0] = tf32_bits(Wl[(size_t)(ks * 8 + tig) * OUT_CH + n]);
            wf[ks][nt][1] = tf32_bits(Wl[(size_t)(ks * 8 + tig + 4) * OUT_CH + n]);
        }
    float bias[4];
#pragma unroll
    for (int nt = 0; nt < 2; nt++)
#pragma unroll
        for (int p = 0; p < 2; p++)
            bias[nt * 2 + p] = bl[nb + nt * 8 + tig * 2 + p];

    for (int i = tid; i < 128 * 32; i += 256) {
        int r = i >> 5, q = i & 31;
        float4 v = make_float4(0.f, 0.f, 0.f, 0.f);
        if (m0 + r < N_NODES)
            v = *(const float4*)(x + (size_t)(m0 + r) * IN_CH + q * 4);
        v.x = rnd_tf32(v.x); v.y = rnd_tf32(v.y);
        v.z = rnd_tf32(v.z); v.w = rnd_tf32(v.w);
        *(float4*)(s_x + r * NL_LDX + q * 4) = v;
    }
    __syncthreads();

    float acc[16][4];
#pragma unroll
    for (int mt = 0; mt < 8; mt++)
#pragma unroll
        for (int nt = 0; nt < 2; nt++) {
            acc[mt * 2 + nt][0] = bias[nt * 2];
            acc[mt * 2 + nt][1] = bias[nt * 2 + 1];
            acc[mt * 2 + nt][2] = bias[nt * 2];
            acc[mt * 2 + nt][3] = bias[nt * 2 + 1];
        }
#pragma unroll
    for (int ks = 0; ks < 16; ks++) {
#pragma unroll
        for (int mt = 0; mt < 8; mt++) {
            uint32_t a[4];
            ldsm_x4(a, sx_u32 + (uint32_t)(mt * 16 * NL_LDX + ks * 8) * 4u + a_off);
            mma_tf32(acc[mt * 2 + 0], a, wf[ks][0][0], wf[ks][0][1]);
            mma_tf32(acc[mt * 2 + 1], a, wf[ks][1][0], wf[ks][1][1]);
        }
    }
#pragma unroll
    for (int mt = 0; mt < 8; mt++)
#pragma unroll
        for (int nt = 0; nt < 2; nt++) {
            int col = nb + nt * 8 + tig * 2;
            int r0 = m0 + mt * 16 + qr;
            float* a = acc[mt * 2 + nt];
            if (r0 < N_NODES)
                *(float2*)(h + (size_t)r0 * OUT_CH + col) = make_float2(a[0], a[1]);
            if (r0 + 8 < N_NODES)
                *(float2*)(h + (size_t)(r0 + 8) * OUT_CH + col) = make_float2(a[2], a[3]);
        }
}

// ---------------------------------------------------------------------------
// WARP-SPECIALIZED edge kernel (R13) + GEMM1 re-tiled 2M x 4N (R14):
//   warps 0-7  (compute): GEMM1 -> H -> GEMM2 -> OUT[i&1]
//   warps 8-15 (scatter): cp.async rbf prefetch for tile t+1,
//                         gather/modulate/red.v4 for tile t-1
// ---------------------------------------------------------------------------
#define LDR 68
#define LDH 132
#define S_W2   0
#define S_RBF0 16384
#define S_RBF1 20736
#define S_H    25088
#define S_OUT0 33536
#define S_OUT1 41984
#define S_B1   50432
#define S_B2   50560
#define SM_FLOATS 50688
#define SM_BYTES (SM_FLOATS * 4)

// rbf prefetch: 64 rows x 64 floats = 1024 cp16 chunks; 256 scatter threads x4
__device__ __forceinline__ void prefetch_rbf(uint32_t sb, int slot,
                                             const float* __restrict__ rbf,
                                             int tile, int tids) {
    const size_t e0 = (size_t)tile * TILE64;
    const uint32_t rb = sb + (uint32_t)(slot ? S_RBF1 : S_RBF0) * 4u;
#pragma unroll
    for (int j = 0; j < 4; j++) {
        int c = j * 256 + tids;
        int r = c >> 4, q = c & 15;
        cp16(rb + (uint32_t)(r * LDR + q * 4) * 4u,
             rbf + (e0 + r) * NUM_RBF + q * 4);
    }
}

__global__ void __launch_bounds__(512, 1)
edge_kernel_ws(const float* __restrict__ rbf, const int* __restrict__ eidx,
               const float* __restrict__ W1, const float* __restrict__ b1g,
               const float* __restrict__ W2, const float* __restrict__ b2g,
               const float* __restrict__ h, float* __restrict__ out,
               int n_ctas) {
    extern __shared__ float sm[];
    const uint32_t sbase = smem_u32(sm);
    uint2* w2s  = (uint2*)(sm + S_W2);
    float* s_H  = sm + S_H;
    float* s_b1 = sm + S_B1;
    float* s_b2 = sm + S_B2;

    const int tid  = threadIdx.x;
    const int wid  = tid >> 5, lane = tid & 31;
    const int qr   = lane >> 2, tig = lane & 3;

    // ---- one-time: W2 fragment image (R9-proven layout) + biases ----
    for (int i = tid; i < 16 * 16 * 32; i += 512) {
        int ks = i >> 9, r = (i >> 5) & 15, ln = i & 31;
        int tg = ln & 3, q = ln >> 2;
        int k0 = ks * 8 + tg, n = r * 8 + q;
        w2s[i] = make_uint2(tf32_bits(W2[(size_t)k0 * OUT_CH + n]),
                            tf32_bits(W2[(size_t)(k0 + 4) * OUT_CH + n]));
    }
    if (tid < 128) { s_b1[tid] = b1g[tid]; s_b2[tid] = b2g[tid]; }

    const int start = blockIdx.x;
    const int step  = n_ctas;

    // compute-warp constants
    const uint32_t aoff_r = ((lane & 15) * LDR + ((lane >> 4) << 2)) * 4u;
    const uint32_t aoff_h = ((lane & 15) * LDH + ((lane >> 4) << 2)) * 4u;
    const uint32_t sH_u32 = sbase + (uint32_t)S_H * 4u;
    // GEMM1 mapping (R14): 2M x 4N — warp M=32 (rows mg1*32), N=32 (cols ng1*32)
    const int mg1 = wid >> 2;            // 0..1
    const int ng1 = wid & 3;             // 0..3
    uint32_t b1f[8][4][2];               // 64 regs, loop-invariant
    if (wid < 8) {
#pragma unroll
        for (int ks = 0; ks < 8; ks++)
#pragma unroll
            for (int n8 = 0; n8 < 4; n8++) {
                int n = ng1 * 32 + n8 * 8 + qr;
                b1f[ks][n8][0] = tf32_bits(W1[(size_t)(ks * 8 + tig) * OUT_CH + n]);
                b1f[ks][n8][1] = tf32_bits(W1[(size_t)(ks * 8 + tig + 4) * OUT_CH + n]);
            }
    } else {                            // scatter warps: prologue rbf prefetch
        prefetch_rbf(sbase, 0, rbf, start, tid - 256);
        cp_commit();
        cp_wait0();
    }
    __syncthreads();

    int i = 0;
    int tile = start;
    for (; tile < NT64; tile += step, i++) {
        if (wid < 8) {
            // ================= COMPUTE GROUP =================
            const uint32_t sR = sbase +
                (uint32_t)((i & 1) ? S_RBF1 : S_RBF0) * 4u;
            float* s_out = sm + ((i & 1) ? S_OUT1 : S_OUT0);

            // GEMM1: H = relu(RBF @ W1 + b1); warp M=32 x N=32, K=64 (R9 layout)
            {
                float acc[2][4][4];
#pragma unroll
                for (int mt = 0; mt < 2; mt++)
#pragma unroll
                    for (int n8 = 0; n8 < 4; n8++)
#pragma unroll
                        for (int q = 0; q < 4; q++) acc[mt][n8][q] = 0.f;
#pragma unroll
                for (int ks = 0; ks < 8; ks++) {
                    uint32_t a0[4], a1[4];
                    ldsm_x4(a0, sR + (uint32_t)((mg1 * 32 + 0) * LDR + ks * 8) * 4u + aoff_r);
                    ldsm_x4(a1, sR + (uint32_t)((mg1 * 32 + 16) * LDR + ks * 8) * 4u + aoff_r);
#pragma unroll
                    for (int n8 = 0; n8 < 4; n8++) {
                        mma_tf32(acc[0][n8], a0, b1f[ks][n8][0], b1f[ks][n8][1]);
                        mma_tf32(acc[1][n8], a1, b1f[ks][n8][0], b1f[ks][n8][1]);
                    }
                }
#pragma unroll
                for (int n8 = 0; n8 < 4; n8++) {
                    int col = ng1 * 32 + n8 * 8 + tig * 2;
                    float2 bz = *(const float2*)(s_b1 + col);
#pragma unroll
                    for (int mt = 0; mt < 2; mt++) {
                        int r0 = mg1 * 32 + mt * 16 + qr;
                        float* a = acc[mt][n8];
                        *(float2*)(s_H + r0 * LDH + col) =
                            make_float2(rnd_tf32(fmaxf(a[0] + bz.x, 0.f)),
                                        rnd_tf32(fmaxf(a[1] + bz.y, 0.f)));
                        *(float2*)(s_H + (r0 + 8) * LDH + col) =
                            make_float2(rnd_tf32(fmaxf(a[2] + bz.x, 0.f)),
                                        rnd_tf32(fmaxf(a[3] + bz.y, 0.f)));
                    }
                }
            }
            bar_compute();   // H write -> H read

            // GEMM2: Wt = H @ W2 + b2; warp = 2M x 4N (M=32, N=32), K=128
            {
                const int mg = wid >> 2;         // 0..1
                const int ng = wid & 3;          // 0..3
                float acc[2][4][4];
#pragma unroll
                for (int mt = 0; mt < 2; mt++)
#pragma unroll
                    for (int n8 = 0; n8 < 4; n8++)
#pragma unroll
                        for (int q = 0; q < 4; q++) acc[mt][n8][q] = 0.f;
#pragma unroll
                for (int ks = 0; ks < 16; ks++) {
                    uint32_t a0[4], a1[4];
                    ldsm_x4(a0, sH_u32 + (uint32_t)((mg * 32 + 0) * LDH + ks * 8) * 4u + aoff_h);
                    ldsm_x4(a1, sH_u32 + (uint32_t)((mg * 32 + 16) * LDH + ks * 8) * 4u + aoff_h);
#pragma unroll
                    for (int n8 = 0; n8 < 4; n8++) {
                        uint2 b = w2s[(ks * 16 + ng * 4 + n8) * 32 + lane];
                        mma_tf32(acc[0][n8], a0, b.x, b.y);
                        mma_tf32(acc[1][n8], a1, b.x, b.y);
                    }
                }
#pragma unroll
                for (int n8 = 0; n8 < 4; n8++) {
                    int col = ng * 32 + n8 * 8 + tig * 2;
                    float2 bz = *(const float2*)(s_b2 + col);
#pragma unroll
                    for (int mt = 0; mt < 2; mt++) {
                        int r0 = mg * 32 + mt * 16 + qr;
                        float* a = acc[mt][n8];
                        *(float2*)(s_out + r0 * LDH + col) =
                            make_float2(a[0] + bz.x, a[1] + bz.y);
                        *(float2*)(s_out + (r0 + 8) * LDH + col) =
                            make_float2(a[2] + bz.x, a[3] + bz.y);
                    }
                }
            }
        } else {
            // ================= SCATTER GROUP =================
            const int sw = wid - 8;              // 0..7, owns 8 edges
            int nx = tile + step;
            bool pf = (nx < NT64);
            if (pf) {
                prefetch_rbf(sbase, (i & 1) ^ 1, rbf, nx, tid - 256);
                cp_commit();
            }
            if (i > 0) {
                const int p = tile - step;
                float* s_outp = sm + (((i - 1) & 1) ? S_OUT1 : S_OUT0);
                const size_t e0 = (size_t)p * TILE64;
                int e8 = sw * 8 + (lane & 7);
                int dstv = eidx[e0 + e8];
                int srcv = eidx[(size_t)N_EDGES + e0 + e8];
#pragma unroll
                for (int half = 0; half < 2; half++) {
                    float4 hv[4];
                    int d4[4];
#pragma unroll
                    for (int u = 0; u < 4; u++) {
                        int u8 = half * 4 + u;
                        int srow = __shfl_sync(0xffffffffu, srcv, u8);
                        d4[u]    = __shfl_sync(0xffffffffu, dstv, u8);
                        hv[u] = *(const float4*)(h + (size_t)srow * OUT_CH + lane * 4);
                    }
#pragma unroll
                    for (int u = 0; u < 4; u++) {
                        int e = sw * 8 + half * 4 + u;
                        float4 wv = *(const float4*)(s_outp + e * LDH + lane * 4);
                        red_add_v4(out + (size_t)d4[u] * OUT_CH + lane * 4,
                                   make_float4(hv[u].x * wv.x, hv[u].y * wv.y,
                                               hv[u].z * wv.z, hv[u].w * wv.w));
                    }
                }
            }
            if (pf) cp_wait0();
        }
        // pipeline boundary: OUT[i&1] published to scatter; rbf[(i+1)&1] ready
        __syncthreads();
    }

    // ---- drain: scatter the last tile this CTA computed ----
    if (i > 0 && wid >= 8) {
        const int sw = wid - 8;
        const int p = tile - step;               // last computed tile
        float* s_outp = sm + (((i - 1) & 1) ? S_OUT1 : S_OUT0);
        const size_t e0 = (size_t)p * TILE64;
        int e8 = sw * 8 + (lane & 7);
        int dstv = eidx[e0 + e8];
        int srcv = eidx[(size_t)N_EDGES + e0 + e8];
#pragma unroll
        for (int half = 0; half < 2; half++) {
            float4 hv[4];
            int d4[4];
#pragma unroll
            for (int u = 0; u < 4; u++) {
                int u8 = half * 4 + u;
                int srow = __shfl_sync(0xffffffffu, srcv, u8);
                d4[u]    = __shfl_sync(0xffffffffu, dstv, u8);
                hv[u] = *(const float4*)(h + (size_t)srow * OUT_CH + lane * 4);
            }
#pragma unroll
            for (int u = 0; u < 4; u++) {
                int e = sw * 8 + half * 4 + u;
                float4 wv = *(const float4*)(s_outp + e * LDH + lane * 4);
                red_add_v4(out + (size_t)d4[u] * OUT_CH + lane * 4,
                           make_float4(hv[u].x * wv.x, hv[u].y * wv.y,
                                       hv[u].z * wv.z, hv[u].w * wv.w));
            }
        }
    }
}

// ---------------------------------------------------------------------------
extern "C" void kernel_launch(void* const* d_in, const int* in_sizes, int n_in,
                              void* d_out, int out_size) {
    const float* x    = (const float*)d_in[0];
    const int*   eidx = (const int*)d_in[1];
    const float* rbf  = (const float*)d_in[2];
    const float* W1   = (const float*)d_in[3];
    const float* b1   = (const float*)d_in[4];
    const float* W2   = (const float*)d_in[5];
    const float* b2   = (const float*)d_in[6];
    const float* Wl   = (const float*)d_in[7];
    const float* bl   = (const float*)d_in[8];
    float* out = (float*)d_out;

    static float* h_ptr = nullptr;
    static int n_sms = 0;
    if (!h_ptr) {
        cudaGetSymbolAddress((void**)&h_ptr, g_h);
        cudaDeviceGetAttribute(&n_sms, cudaDevAttrMultiProcessorCount, 0);
        cudaFuncSetAttribute(edge_kernel_ws,
                             cudaFuncAttributeMaxDynamicSharedMemorySize, SM_BYTES);
        cudaFuncSetAttribute(node_linear_mma,
                             cudaFuncAttributeMaxDynamicSharedMemorySize, NL_SMEM_BYTES);
    }

    cudaMemsetAsync(d_out, 0, (size_t)N_NODES * OUT_CH * sizeof(float), 0);
    node_linear_mma<<<(N_NODES + 127) / 128, 256, NL_SMEM_BYTES>>>(x, Wl, bl, h_ptr);
    edge_kernel_ws<<<n_sms, 512, SM_BYTES>>>(rbf, eidx, W1, b1, W2, b2,
                                             h_ptr, out, n_sms);
}

// round 15
// speedup vs baseline: 1.2364x; 1.2364x over previous
#include <cuda_runtime.h>
#include <cuda_fp16.h>
#include <cstdint>

#define N_NODES 40000
#define N_EDGES 640000
#define IN_CH   128
#define OUT_CH  128
#define NUM_RBF 64
#define TILE64  64
#define NT64    (N_EDGES / TILE64)     // 10000

// ---------------- device scratch (no allocs allowed) ----------------
__device__ float g_h[(size_t)N_NODES * OUT_CH];      // x @ Wl + bl

// ---------------- helpers ----------------
__device__ __forceinline__ float rnd_tf32(float x) {
    float r;
    asm("cvt.rna.tf32.f32 %0, %1;" : "=f"(r) : "f"(x));
    return r;
}
__device__ __forceinline__ uint32_t tf32_bits(float x) {
    return __float_as_uint(rnd_tf32(x));
}
// pack two floats to f16x2: lower half = lo, upper = hi
__device__ __forceinline__ uint32_t pack_h2(float lo, float hi) {
    uint32_t r;
    asm("cvt.rn.f16x2.f32 %0, %1, %2;" : "=r"(r) : "f"(hi), "f"(lo));
    return r;
}
__device__ __forceinline__ uint32_t smem_u32(const void* p) {
    uint32_t a;
    asm("{ .reg .u64 t; cvta.to.shared.u64 t, %1; cvt.u32.u64 %0, t; }"
        : "=r"(a) : "l"(p));
    return a;
}
__device__ __forceinline__ void red_add_v4(float* addr, float4 v) {
    asm volatile("red.global.add.v4.f32 [%0], {%1,%2,%3,%4};"
                 :: "l"(addr), "f"(v.x), "f"(v.y), "f"(v.z), "f"(v.w) : "memory");
}
__device__ __forceinline__ void cp16(uint32_t saddr, const void* g) {
    asm volatile("cp.async.cg.shared.global [%0], [%1], 16;"
                 :: "r"(saddr), "l"(g) : "memory");
}
__device__ __forceinline__ void cp_commit() {
    asm volatile("cp.async.commit_group;" ::: "memory");
}
__device__ __forceinline__ void cp_wait0() {
    asm volatile("cp.async.wait_group 0;" ::: "memory");
}
__device__ __forceinline__ void bar_compute() {       // warps 0-7 only
    asm volatile("bar.sync 1, 256;" ::: "memory");
}
// mma.sync m16n8k16 f16 (baseline PTX, sm_80+): 2x K per instruction vs tf32
__device__ __forceinline__ void mma_f16(float d[4], const uint32_t a[4],
                                        uint32_t b0, uint32_t b1) {
    asm volatile(
        "mma.sync.aligned.m16n8k16.row.col.f32.f16.f16.f32 "
        "{%0,%1,%2,%3}, {%4,%5,%6,%7}, {%8,%9}, {%0,%1,%2,%3};"
        : "+f"(d[0]), "+f"(d[1]), "+f"(d[2]), "+f"(d[3])
        : "r"(a[0]), "r"(a[1]), "r"(a[2]), "r"(a[3]), "r"(b0), "r"(b1));
}
// mma.sync m16n8k8 tf32 (node_linear keeps the proven tf32 path)
__device__ __forceinline__ void mma_tf32(float d[4], const uint32_t a[4],
                                         uint32_t b0, uint32_t b1) {
    asm volatile(
        "mma.sync.aligned.m16n8k8.row.col.f32.tf32.tf32.f32 "
        "{%0,%1,%2,%3}, {%4,%5,%6,%7}, {%8,%9}, {%0,%1,%2,%3};"
        : "+f"(d[0]), "+f"(d[1]), "+f"(d[2]), "+f"(d[3])
        : "r"(a[0]), "r"(a[1]), "r"(a[2]), "r"(a[3]), "r"(b0), "r"(b1));
}
__device__ __forceinline__ void ldsm_x4(uint32_t a[4], uint32_t saddr) {
    asm volatile("ldmatrix.sync.aligned.m8n8.x4.shared.b16 {%0,%1,%2,%3}, [%4];"
                 : "=r"(a[0]), "=r"(a[1]), "=r"(a[2]), "=r"(a[3]) : "r"(saddr));
}

// ---------------------------------------------------------------------------
// node linear: h = x @ Wl + bl via tf32 mma (unchanged, proven)
// ---------------------------------------------------------------------------
#define NL_LDX 132
#define NL_SMEM_BYTES (128 * NL_LDX * 4)

__global__ void __launch_bounds__(256)
node_linear_mma(const float* __restrict__ x, const float* __restrict__ Wl,
                const float* __restrict__ bl, float* __restrict__ h) {
    extern __shared__ float s_x[];
    const int tid = threadIdx.x;
    const int wid = tid >> 5, lane = tid & 31;
    const int qr = lane >> 2, tig = lane & 3;
    const int nb = wid * 16;
    const int m0 = blockIdx.x * 128;
    const uint32_t sx_u32 = smem_u32(s_x);
    const uint32_t a_off = ((lane & 15) * NL_LDX + ((lane >> 4) << 2)) * 4u;

    uint32_t wf[16][2][2];
#pragma unroll
    for (int ks = 0; ks < 16; ks++)
#pragma unroll
        for (int nt = 0; nt < 2; nt++) {
            int n = nb + nt * 8 + qr;
            wf[ks][nt][0] = tf32_bits(Wl[(size_t)(ks * 8 + tig) * OUT_CH + n]);
            wf[ks][nt][1] = tf32_bits(Wl[(size_t)(ks * 8 + tig + 4) * OUT_CH + n]);
        }
    float bias[4];
#pragma unroll
    for (int nt = 0; nt < 2; nt++)
#pragma unroll
        for (int p = 0; p < 2; p++)
            bias[nt * 2 + p] = bl[nb + nt * 8 + tig * 2 + p];

    for (int i = tid; i < 128 * 32; i += 256) {
        int r = i >> 5, q = i & 31;
        float4 v = make_float4(0.f, 0.f, 0.f, 0.f);
        if (m0 + r < N_NODES)
            v = *(const float4*)(x + (size_t)(m0 + r) * IN_CH + q * 4);
        v.x = rnd_tf32(v.x); v.y = rnd_tf32(v.y);
        v.z = rnd_tf32(v.z); v.w = rnd_tf32(v.w);
        *(float4*)(s_x + r * NL_LDX + q * 4) = v;
    }
    __syncthreads();

    float acc[16][4];
#pragma unroll
    for (int mt = 0; mt < 8; mt++)
#pragma unroll
        for (int nt = 0; nt < 2; nt++) {
            acc[mt * 2 + nt][0] = bias[nt * 2];
            acc[mt * 2 + nt][1] = bias[nt * 2 + 1];
            acc[mt * 2 + nt][2] = bias[nt * 2];
            acc[mt * 2 + nt][3] = bias[nt * 2 + 1];
        }
#pragma unroll
    for (int ks = 0; ks < 16; ks++) {
#pragma unroll
        for (int mt = 0; mt < 8; mt++) {
            uint32_t a[4];
            ldsm_x4(a, sx_u32 + (uint32_t)(mt * 16 * NL_LDX + ks * 8) * 4u + a_off);
            mma_tf32(acc[mt * 2 + 0], a, wf[ks][0][0], wf[ks][0][1]);
            mma_tf32(acc[mt * 2 + 1], a, wf[ks][1][0], wf[ks][1][1]);
        }
    }
#pragma unroll
    for (int mt = 0; mt < 8; mt++)
#pragma unroll
        for (int nt = 0; nt < 2; nt++) {
            int col = nb + nt * 8 + tig * 2;
            int r0 = m0 + mt * 16 + qr;
            float* a = acc[mt * 2 + nt];
            if (r0 < N_NODES)
                *(float2*)(h + (size_t)r0 * OUT_CH + col) = make_float2(a[0], a[1]);
            if (r0 + 8 < N_NODES)
                *(float2*)(h + (size_t)(r0 + 8) * OUT_CH + col) = make_float2(a[2], a[3]);
        }
}

// ---------------------------------------------------------------------------
// WARP-SPECIALIZED edge kernel (R13 skeleton) with FP16 MMA datapath (R15):
//   warps 0-7  (compute): GEMM1 fp16 -> H(fp16) -> GEMM2 fp16 -> OUT[i&1](fp32)
//   warps 8-15 (scatter): cp.async fp32 rbf staging for t+1, convert->fp16
//                         strip; gather/modulate/red.v4 for tile t-1
//
// smem floats: W2img(f16 frags) 8192 | stage 4096 | rbf16 2x2304 |
//              H16 4352 | OUT 2x8448 | b1/b2 256  = 38400 (153.6 KB)
// ---------------------------------------------------------------------------
#define LDRH 72            // rbf fp16 row stride (halves); 144B % 128 = 16 ok
#define LDHH 136           // H fp16 row stride (halves); 272B % 128 = 16 ok
#define LDO  132           // OUT fp32 row stride
#define S_W2    0
#define S_STAGE 8192
#define S_R16_0 12288
#define S_R16_1 14592
#define S_H16   16896
#define S_OUT0  21248
#define S_OUT1  29696
#define S_B1    38144
#define S_B2    38272
#define SM_FLOATS 38400
#define SM_BYTES (SM_FLOATS * 4)

// stage prefetch: 64 rows x 64 fp32 = 1024 cp16 chunks; 256 scatter threads x4
__device__ __forceinline__ void prefetch_stage(uint32_t sb,
                                               const float* __restrict__ rbf,
                                               int tile, int tids) {
    const size_t e0 = (size_t)tile * TILE64;
    const uint32_t st = sb + (uint32_t)S_STAGE * 4u;
#pragma unroll
    for (int j = 0; j < 4; j++) {
        int c = j * 256 + tids;
        cp16(st + (uint32_t)c * 16u, rbf + e0 * NUM_RBF + c * 4);
    }
}
// convert staging (fp32 linear 64x64) -> fp16 strip (LDRH-padded)
__device__ __forceinline__ void convert_stage(float* sm, uint32_t sb,
                                              int slot, int tids) {
    const float* stage = sm + S_STAGE;
    char* dst = (char*)sm + (size_t)(slot ? S_R16_1 : S_R16_0) * 4;
#pragma unroll
    for (int j = 0; j < 4; j++) {
        int idx = j * 1024 + tids * 4;
        int r = idx >> 6, c = idx & 63;
        float4 v = *(const float4*)(stage + idx);
        uint2 p;
        p.x = pack_h2(v.x, v.y);
        p.y = pack_h2(v.z, v.w);
        *(uint2*)(dst + (r * LDRH + c) * 2) = p;
    }
}

__global__ void __launch_bounds__(512, 1)
edge_kernel_f16(const float* __restrict__ rbf, const int* __restrict__ eidx,
                const float* __restrict__ W1, const float* __restrict__ b1g,
                const float* __restrict__ W2, const float* __restrict__ b2g,
                const float* __restrict__ h, float* __restrict__ out,
                int n_ctas) {
    extern __shared__ float sm[];
    const uint32_t sbase = smem_u32(sm);
    uint2* w2s  = (uint2*)(sm + S_W2);
    float* s_b1 = sm + S_B1;
    float* s_b2 = sm + S_B2;

    const int tid  = threadIdx.x;
    const int wid  = tid >> 5, lane = tid & 31;
    const int qr   = lane >> 2, tig = lane & 3;

    // ---- one-time: W2 fp16 fragment image (m16n8k16 B layout) + biases ----
    // frag for (ks, n8) at [(ks*16+n8)*32+lane]:
    //   n = n8*8 + lane/4; b0 = {W2[ks*16+2t][n], [ks*16+2t+1][n]},
    //   b1 = same + 8 (t = lane%4)
    for (int i = tid; i < 8 * 16 * 32; i += 512) {
        int ks = i >> 9, r = (i >> 5) & 15, ln = i & 31;
        int n = r * 8 + (ln >> 2);
        int kb = ks * 16 + 2 * (ln & 3);
        w2s[i] = make_uint2(
            pack_h2(W2[(size_t)kb * OUT_CH + n], W2[(size_t)(kb + 1) * OUT_CH + n]),
            pack_h2(W2[(size_t)(kb + 8) * OUT_CH + n], W2[(size_t)(kb + 9) * OUT_CH + n]));
    }
    if (tid < 128) { s_b1[tid] = b1g[tid]; s_b2[tid] = b2g[tid]; }

    const int start = blockIdx.x;
    const int step  = n_ctas;

    // fp16 ldmatrix lane offsets (bytes): (lane&15)*ld + (lane>=16)*8 halves
    const uint32_t aoff_r = ((lane & 15) * LDRH + ((lane >> 4) << 3)) * 2u;
    const uint32_t aoff_h = ((lane & 15) * LDHH + ((lane >> 4) << 3)) * 2u;
    const uint32_t sH_u32 = sbase + (uint32_t)S_H16 * 4u;

    // GEMM1 mapping: 2M x 4N (warp M=32, N=32); b1f fp16 frags in regs
    const int mg1 = wid >> 2;            // 0..1
    const int ng1 = wid & 3;             // 0..3
    uint32_t b1f[4][4][2];               // K=64 -> 4 k16 steps; 32 regs
    if (wid < 8) {
#pragma unroll
        for (int ks = 0; ks < 4; ks++)
#pragma unroll
            for (int n8 = 0; n8 < 4; n8++) {
                int n = ng1 * 32 + n8 * 8 + qr;
                int kb = ks * 16 + 2 * tig;
                b1f[ks][n8][0] = pack_h2(W1[(size_t)kb * OUT_CH + n],
                                         W1[(size_t)(kb + 1) * OUT_CH + n]);
                b1f[ks][n8][1] = pack_h2(W1[(size_t)(kb + 8) * OUT_CH + n],
                                         W1[(size_t)(kb + 9) * OUT_CH + n]);
            }
    } else {
        // scatter warps prologue: stage tile `start`, convert into slot 0
        prefetch_stage(sbase, rbf, start, tid - 256);
        cp_commit();
        cp_wait0();
        convert_stage(sm, sbase, 0, tid - 256);
    }
    __syncthreads();

    int i = 0;
    int tile = start;
    for (; tile < NT64; tile += step, i++) {
        if (wid < 8) {
            // ================= COMPUTE GROUP =================
            const uint32_t sR = sbase +
                (uint32_t)((i & 1) ? S_R16_1 : S_R16_0) * 4u;
            float* s_out = sm + ((i & 1) ? S_OUT1 : S_OUT0);
            char* s_H16 = (char*)sm + (size_t)S_H16 * 4;

            // GEMM1: H = relu(RBF @ W1 + b1); warp M=32 x N=32, K=64 (4 k16)
            {
                float acc[2][4][4];
#pragma unroll
                for (int mt = 0; mt < 2; mt++)
#pragma unroll
                    for (int n8 = 0; n8 < 4; n8++)
#pragma unroll
                        for (int q = 0; q < 4; q++) acc[mt][n8][q] = 0.f;
#pragma unroll
                for (int ks = 0; ks < 4; ks++) {
                    uint32_t a0[4], a1[4];
                    ldsm_x4(a0, sR + (uint32_t)((mg1 * 32 + 0) * LDRH + ks * 16) * 2u + aoff_r);
                    ldsm_x4(a1, sR + (uint32_t)((mg1 * 32 + 16) * LDRH + ks * 16) * 2u + aoff_r);
#pragma unroll
                    for (int n8 = 0; n8 < 4; n8++) {
                        mma_f16(acc[0][n8], a0, b1f[ks][n8][0], b1f[ks][n8][1]);
                        mma_f16(acc[1][n8], a1, b1f[ks][n8][0], b1f[ks][n8][1]);
                    }
                }
                // epilogue -> H fp16 (bias, relu)
#pragma unroll
                for (int n8 = 0; n8 < 4; n8++) {
                    int col = ng1 * 32 + n8 * 8 + tig * 2;
                    float2 bz = *(const float2*)(s_b1 + col);
#pragma unroll
                    for (int mt = 0; mt < 2; mt++) {
                        int r0 = mg1 * 32 + mt * 16 + qr;
                        float* a = acc[mt][n8];
                        *(uint32_t*)(s_H16 + (r0 * LDHH + col) * 2) =
                            pack_h2(fmaxf(a[0] + bz.x, 0.f), fmaxf(a[1] + bz.y, 0.f));
                        *(uint32_t*)(s_H16 + ((r0 + 8) * LDHH + col) * 2) =
                            pack_h2(fmaxf(a[2] + bz.x, 0.f), fmaxf(a[3] + bz.y, 0.f));
                    }
                }
            }
            bar_compute();   // H write -> H read

            // GEMM2: Wt = H @ W2 + b2; warp 2M x 4N (M=32, N=32), K=128 (8 k16)
            {
                const int mg = wid >> 2;
                const int ng = wid & 3;
                float acc[2][4][4];
#pragma unroll
                for (int mt = 0; mt < 2; mt++)
#pragma unroll
                    for (int n8 = 0; n8 < 4; n8++)
#pragma unroll
                        for (int q = 0; q < 4; q++) acc[mt][n8][q] = 0.f;
#pragma unroll
                for (int ks = 0; ks < 8; ks++) {
                    uint32_t a0[4], a1[4];
                    ldsm_x4(a0, sH_u32 + (uint32_t)((mg * 32 + 0) * LDHH + ks * 16) * 2u + aoff_h);
                    ldsm_x4(a1, sH_u32 + (uint32_t)((mg * 32 + 16) * LDHH + ks * 16) * 2u + aoff_h);
#pragma unroll
                    for (int n8 = 0; n8 < 4; n8++) {
                        uint2 b = w2s[(ks * 16 + ng * 4 + n8) * 32 + lane];
                        mma_f16(acc[0][n8], a0, b.x, b.y);
                        mma_f16(acc[1][n8], a1, b.x, b.y);
                    }
                }
#pragma unroll
                for (int n8 = 0; n8 < 4; n8++) {
                    int col = ng * 32 + n8 * 8 + tig * 2;
                    float2 bz = *(const float2*)(s_b2 + col);
#pragma unroll
                    for (int mt = 0; mt < 2; mt++) {
                        int r0 = mg * 32 + mt * 16 + qr;
                        float* a = acc[mt][n8];
                        *(float2*)(s_out + r0 * LDO + col) =
                            make_float2(a[0] + bz.x, a[1] + bz.y);
                        *(float2*)(s_out + (r0 + 8) * LDO + col) =
                            make_float2(a[2] + bz.x, a[3] + bz.y);
                    }
                }
            }
        } else {
            // ================= SCATTER GROUP =================
            const int sw = wid - 8;              // 0..7, owns 8 edges
            const int tids = tid - 256;
            int nx = tile + step;
            bool pf = (nx < NT64);
            if (pf) {
                prefetch_stage(sbase, rbf, nx, tids);
                cp_commit();
            }
            if (i > 0) {
                const int p = tile - step;
                float* s_outp = sm + (((i - 1) & 1) ? S_OUT1 : S_OUT0);
                const size_t e0 = (size_t)p * TILE64;
                int e8 = sw * 8 + (lane & 7);
                int dstv = eidx[e0 + e8];
                int srcv = eidx[(size_t)N_EDGES + e0 + e8];
#pragma unroll
                for (int half = 0; half < 2; half++) {
                    float4 hv[4];
                    int d4[4];
#pragma unroll
                    for (int u = 0; u < 4; u++) {
                        int u8 = half * 4 + u;
                        int srow = __shfl_sync(0xffffffffu, srcv, u8);
                        d4[u]    = __shfl_sync(0xffffffffu, dstv, u8);
                        hv[u] = *(const float4*)(h + (size_t)srow * OUT_CH + lane * 4);
                    }
#pragma unroll
                    for (int u = 0; u < 4; u++) {
                        int e = sw * 8 + half * 4 + u;
                        float4 wv = *(const float4*)(s_outp + e * LDO + lane * 4);
                        red_add_v4(out + (size_t)d4[u] * OUT_CH + lane * 4,
                                   make_float4(hv[u].x * wv.x, hv[u].y * wv.y,
                                               hv[u].z * wv.z, hv[u].w * wv.w));
                    }
                }
            }
            if (pf) {
                cp_wait0();
                convert_stage(sm, sbase, (i + 1) & 1, tids);
            }
        }
        // pipeline boundary: OUT[i&1] -> scatter; rbf16[(i+1)&1] -> compute
        __syncthreads();
    }

    // ---- drain: scatter the last tile this CTA computed ----
    if (i > 0 && wid >= 8) {
        const int sw = wid - 8;
        const int p = tile - step;
        float* s_outp = sm + (((i - 1) & 1) ? S_OUT1 : S_OUT0);
        const size_t e0 = (size_t)p * TILE64;
        int e8 = sw * 8 + (lane & 7);
        int dstv = eidx[e0 + e8];
        int srcv = eidx[(size_t)N_EDGES + e0 + e8];
#pragma unroll
        for (int half = 0; half < 2; half++) {
            float4 hv[4];
            int d4[4];
#pragma unroll
            for (int u = 0; u < 4; u++) {
                int u8 = half * 4 + u;
                int srow = __shfl_sync(0xffffffffu, srcv, u8);
                d4[u]    = __shfl_sync(0xffffffffu, dstv, u8);
                hv[u] = *(const float4*)(h + (size_t)srow * OUT_CH + lane * 4);
            }
#pragma unroll
            for (int u = 0; u < 4; u++) {
                int e = sw * 8 + half * 4 + u;
                float4 wv = *(const float4*)(s_outp + e * LDO + lane * 4);
                red_add_v4(out + (size_t)d4[u] * OUT_CH + lane * 4,
                           make_float4(hv[u].x * wv.x, hv[u].y * wv.y,
                                       hv[u].z * wv.z, hv[u].w * wv.w));
            }
        }
    }
}

// ---------------------------------------------------------------------------
extern "C" void kernel_launch(void* const* d_in, const int* in_sizes, int n_in,
                              void* d_out, int out_size) {
    const float* x    = (const float*)d_in[0];
    const int*   eidx = (const int*)d_in[1];
    const float* rbf  = (const float*)d_in[2];
    const float* W1   = (const float*)d_in[3];
    const float* b1   = (const float*)d_in[4];
    const float* W2   = (const float*)d_in[5];
    const float* b2   = (const float*)d_in[6];
    const float* Wl   = (const float*)d_in[7];
    const float* bl   = (const float*)d_in[8];
    float* out = (float*)d_out;

    static float* h_ptr = nullptr;
    static int n_sms = 0;
    if (!h_ptr) {
        cudaGetSymbolAddress((void**)&h_ptr, g_h);
        cudaDeviceGetAttribute(&n_sms, cudaDevAttrMultiProcessorCount, 0);
        cudaFuncSetAttribute(edge_kernel_f16,
                             cudaFuncAttributeMaxDynamicSharedMemorySize, SM_BYTES);
        cudaFuncSetAttribute(node_linear_mma,
                             cudaFuncAttributeMaxDynamicSharedMemorySize, NL_SMEM_BYTES);
    }

    cudaMemsetAsync(d_out, 0, (size_t)N_NODES * OUT_CH * sizeof(float), 0);
    node_linear_mma<<<(N_NODES + 127) / 128, 256, NL_SMEM_BYTES>>>(x, Wl, bl, h_ptr);
    edge_kernel_f16<<<n_sms, 512, SM_BYTES>>>(rbf, eidx, W1, b1, W2, b2,
                                              h_ptr, out, n_sms);
}

// round 16
// speedup vs baseline: 1.3490x; 1.0910x over previous
#include <cuda_runtime.h>
#include <cuda_fp16.h>
#include <cstdint>

#define N_NODES 40000
#define N_EDGES 640000
#define IN_CH   128
#define OUT_CH  128
#define NUM_RBF 64
#define TILE64  64
#define NT64    (N_EDGES / TILE64)     // 10000

// ---------------- device scratch (no allocs allowed) ----------------
__device__ __half g_h16[(size_t)N_NODES * OUT_CH];   // x @ Wl + bl, fp16

// ---------------- helpers ----------------
// pack two floats to f16x2: lower half = lo, upper = hi (proven R15 mapping)
__device__ __forceinline__ uint32_t pack_h2(float lo, float hi) {
    uint32_t r;
    asm("cvt.rn.f16x2.f32 %0, %1, %2;" : "=r"(r) : "f"(hi), "f"(lo));
    return r;
}
__device__ __forceinline__ uint32_t smem_u32(const void* p) {
    uint32_t a;
    asm("{ .reg .u64 t; cvta.to.shared.u64 t, %1; cvt.u32.u64 %0, t; }"
        : "=r"(a) : "l"(p));
    return a;
}
__device__ __forceinline__ void red_add_v4(float* addr, float4 v) {
    asm volatile("red.global.add.v4.f32 [%0], {%1,%2,%3,%4};"
                 :: "l"(addr), "f"(v.x), "f"(v.y), "f"(v.z), "f"(v.w) : "memory");
}
__device__ __forceinline__ void cp16(uint32_t saddr, const void* g) {
    asm volatile("cp.async.cg.shared.global [%0], [%1], 16;"
                 :: "r"(saddr), "l"(g) : "memory");
}
__device__ __forceinline__ void cp_commit() {
    asm volatile("cp.async.commit_group;" ::: "memory");
}
__device__ __forceinline__ void cp_wait0() {
    asm volatile("cp.async.wait_group 0;" ::: "memory");
}
__device__ __forceinline__ void bar_compute() {       // warps 0-7 only
    asm volatile("bar.sync 1, 256;" ::: "memory");
}
// mma.sync m16n8k16 f16 (baseline PTX, sm_80+)
__device__ __forceinline__ void mma_f16(float d[4], const uint32_t a[4],
                                        uint32_t b0, uint32_t b1) {
    asm volatile(
        "mma.sync.aligned.m16n8k16.row.col.f32.f16.f16.f32 "
        "{%0,%1,%2,%3}, {%4,%5,%6,%7}, {%8,%9}, {%0,%1,%2,%3};"
        : "+f"(d[0]), "+f"(d[1]), "+f"(d[2]), "+f"(d[3])
        : "r"(a[0]), "r"(a[1]), "r"(a[2]), "r"(a[3]), "r"(b0), "r"(b1));
}
__device__ __forceinline__ void ldsm_x4(uint32_t a[4], uint32_t saddr) {
    asm volatile("ldmatrix.sync.aligned.m8n8.x4.shared.b16 {%0,%1,%2,%3}, [%4];"
                 : "=r"(a[0]), "=r"(a[1]), "=r"(a[2]), "=r"(a[3]) : "r"(saddr));
}
// unpack fp16 h row chunk (4 halves) -> float4
__device__ __forceinline__ float4 h4_to_f4(uint2 p) {
    float2 lo = __half22float2(*(const __half2*)&p.x);
    float2 hi = __half22float2(*(const __half2*)&p.y);
    return make_float4(lo.x, lo.y, hi.x, hi.y);
}

// ---------------------------------------------------------------------------
// node linear fp16: h16 = fp16(x @ Wl + bl) via m16n8k16.
// 128-row tile / CTA, 8 warps (warp = M128-slice x N16), K=128 = 8 k16 steps.
// ---------------------------------------------------------------------------
#define NL_LDXH 136     // x fp16 row stride in halves; 272B % 128 = 16 (cf-free)
#define NL_SMEM_BYTES (128 * NL_LDXH * 2)

__global__ void __launch_bounds__(256)
node_linear_f16(const float* __restrict__ x, const float* __restrict__ Wl,
                const float* __restrict__ bl, __half* __restrict__ h16) {
    extern __shared__ char smn[];
    char* s_x = smn;
    const int tid = threadIdx.x;
    const int wid = tid >> 5, lane = tid & 31;
    const int qr = lane >> 2, tig = lane & 3;
    const int nb = wid * 16;
    const int m0 = blockIdx.x * 128;
    const uint32_t sx_u32 = smem_u32(s_x);
    const uint32_t a_off = ((lane & 15) * NL_LDXH + ((lane >> 4) << 3)) * 2u;

    // Wl fp16 fragments (proven R15 B layout): K=128 -> 8 k16 steps
    uint32_t wf[8][2][2];
#pragma unroll
    for (int ks = 0; ks < 8; ks++)
#pragma unroll
        for (int nt = 0; nt < 2; nt++) {
            int n = nb + nt * 8 + qr;
            int kb = ks * 16 + 2 * tig;
            wf[ks][nt][0] = pack_h2(Wl[(size_t)kb * OUT_CH + n],
                                    Wl[(size_t)(kb + 1) * OUT_CH + n]);
            wf[ks][nt][1] = pack_h2(Wl[(size_t)(kb + 8) * OUT_CH + n],
                                    Wl[(size_t)(kb + 9) * OUT_CH + n]);
        }
    float bias[4];
#pragma unroll
    for (int nt = 0; nt < 2; nt++)
#pragma unroll
        for (int p = 0; p < 2; p++)
            bias[nt * 2 + p] = bl[nb + nt * 8 + tig * 2 + p];

    // x tile -> fp16 smem
    for (int i = tid; i < 128 * 32; i += 256) {
        int r = i >> 5, q = i & 31;           // q indexes float4 groups
        float4 v = make_float4(0.f, 0.f, 0.f, 0.f);
        if (m0 + r < N_NODES)
            v = *(const float4*)(x + (size_t)(m0 + r) * IN_CH + q * 4);
        uint2 p;
        p.x = pack_h2(v.x, v.y);
        p.y = pack_h2(v.z, v.w);
        *(uint2*)(s_x + (r * NL_LDXH + q * 4) * 2) = p;
    }
    __syncthreads();

    float acc[16][4];
#pragma unroll
    for (int mt = 0; mt < 8; mt++)
#pragma unroll
        for (int nt = 0; nt < 2; nt++) {
            acc[mt * 2 + nt][0] = bias[nt * 2];
            acc[mt * 2 + nt][1] = bias[nt * 2 + 1];
            acc[mt * 2 + nt][2] = bias[nt * 2];
            acc[mt * 2 + nt][3] = bias[nt * 2 + 1];
        }
#pragma unroll
    for (int ks = 0; ks < 8; ks++) {
#pragma unroll
        for (int mt = 0; mt < 8; mt++) {
            uint32_t a[4];
            ldsm_x4(a, sx_u32 + (uint32_t)(mt * 16 * NL_LDXH + ks * 16) * 2u + a_off);
            mma_f16(acc[mt * 2 + 0], a, wf[ks][0][0], wf[ks][0][1]);
            mma_f16(acc[mt * 2 + 1], a, wf[ks][1][0], wf[ks][1][1]);
        }
    }
#pragma unroll
    for (int mt = 0; mt < 8; mt++)
#pragma unroll
        for (int nt = 0; nt < 2; nt++) {
            int col = nb + nt * 8 + tig * 2;
            int r0 = m0 + mt * 16 + qr;
            float* a = acc[mt * 2 + nt];
            if (r0 < N_NODES)
                *(uint32_t*)(h16 + (size_t)r0 * OUT_CH + col) = pack_h2(a[0], a[1]);
            if (r0 + 8 < N_NODES)
                *(uint32_t*)(h16 + (size_t)(r0 + 8) * OUT_CH + col) = pack_h2(a[2], a[3]);
        }
}

// ---------------------------------------------------------------------------
// WARP-SPECIALIZED fp16 edge kernel (R15, unchanged except h is fp16):
//   warps 0-7  (compute): GEMM1 fp16 -> H(fp16) -> GEMM2 fp16 -> OUT[i&1](fp32)
//   warps 8-15 (scatter): cp.async fp32 rbf staging for t+1, convert->fp16
//                         strip; gather fp16 h / modulate / red.v4 for t-1
// ---------------------------------------------------------------------------
#define LDRH 72
#define LDHH 136
#define LDO  132
#define S_W2    0
#define S_STAGE 8192
#define S_R16_0 12288
#define S_R16_1 14592
#define S_H16   16896
#define S_OUT0  21248
#define S_OUT1  29696
#define S_B1    38144
#define S_B2    38272
#define SM_FLOATS 38400
#define SM_BYTES (SM_FLOATS * 4)

__device__ __forceinline__ void prefetch_stage(uint32_t sb,
                                               const float* __restrict__ rbf,
                                               int tile, int tids) {
    const size_t e0 = (size_t)tile * TILE64;
    const uint32_t st = sb + (uint32_t)S_STAGE * 4u;
#pragma unroll
    for (int j = 0; j < 4; j++) {
        int c = j * 256 + tids;
        cp16(st + (uint32_t)c * 16u, rbf + e0 * NUM_RBF + c * 4);
    }
}
__device__ __forceinline__ void convert_stage(float* sm, uint32_t sb,
                                              int slot, int tids) {
    const float* stage = sm + S_STAGE;
    char* dst = (char*)sm + (size_t)(slot ? S_R16_1 : S_R16_0) * 4;
#pragma unroll
    for (int j = 0; j < 4; j++) {
        int idx = j * 1024 + tids * 4;
        int r = idx >> 6, c = idx & 63;
        float4 v = *(const float4*)(stage + idx);
        uint2 p;
        p.x = pack_h2(v.x, v.y);
        p.y = pack_h2(v.z, v.w);
        *(uint2*)(dst + (r * LDRH + c) * 2) = p;
    }
}

__global__ void __launch_bounds__(512, 1)
edge_kernel_f16(const float* __restrict__ rbf, const int* __restrict__ eidx,
                const float* __restrict__ W1, const float* __restrict__ b1g,
                const float* __restrict__ W2, const float* __restrict__ b2g,
                const __half* __restrict__ h16, float* __restrict__ out,
                int n_ctas) {
    extern __shared__ float sm[];
    const uint32_t sbase = smem_u32(sm);
    uint2* w2s  = (uint2*)(sm + S_W2);
    float* s_b1 = sm + S_B1;
    float* s_b2 = sm + S_B2;

    const int tid  = threadIdx.x;
    const int wid  = tid >> 5, lane = tid & 31;
    const int qr   = lane >> 2, tig = lane & 3;

    // ---- one-time: W2 fp16 fragment image + biases ----
    for (int i = tid; i < 8 * 16 * 32; i += 512) {
        int ks = i >> 9, r = (i >> 5) & 15, ln = i & 31;
        int n = r * 8 + (ln >> 2);
        int kb = ks * 16 + 2 * (ln & 3);
        w2s[i] = make_uint2(
            pack_h2(W2[(size_t)kb * OUT_CH + n], W2[(size_t)(kb + 1) * OUT_CH + n]),
            pack_h2(W2[(size_t)(kb + 8) * OUT_CH + n], W2[(size_t)(kb + 9) * OUT_CH + n]));
    }
    if (tid < 128) { s_b1[tid] = b1g[tid]; s_b2[tid] = b2g[tid]; }

    const int start = blockIdx.x;
    const int step  = n_ctas;

    const uint32_t aoff_r = ((lane & 15) * LDRH + ((lane >> 4) << 3)) * 2u;
    const uint32_t aoff_h = ((lane & 15) * LDHH + ((lane >> 4) << 3)) * 2u;
    const uint32_t sH_u32 = sbase + (uint32_t)S_H16 * 4u;

    const int mg1 = wid >> 2;
    const int ng1 = wid & 3;
    uint32_t b1f[4][4][2];
    if (wid < 8) {
#pragma unroll
        for (int ks = 0; ks < 4; ks++)
#pragma unroll
            for (int n8 = 0; n8 < 4; n8++) {
                int n = ng1 * 32 + n8 * 8 + qr;
                int kb = ks * 16 + 2 * tig;
                b1f[ks][n8][0] = pack_h2(W1[(size_t)kb * OUT_CH + n],
                                         W1[(size_t)(kb + 1) * OUT_CH + n]);
                b1f[ks][n8][1] = pack_h2(W1[(size_t)(kb + 8) * OUT_CH + n],
                                         W1[(size_t)(kb + 9) * OUT_CH + n]);
            }
    } else {
        prefetch_stage(sbase, rbf, start, tid - 256);
        cp_commit();
        cp_wait0();
        convert_stage(sm, sbase, 0, tid - 256);
    }
    __syncthreads();

    int i = 0;
    int tile = start;
    for (; tile < NT64; tile += step, i++) {
        if (wid < 8) {
            // ================= COMPUTE GROUP =================
            const uint32_t sR = sbase +
                (uint32_t)((i & 1) ? S_R16_1 : S_R16_0) * 4u;
            float* s_out = sm + ((i & 1) ? S_OUT1 : S_OUT0);
            char* s_H16 = (char*)sm + (size_t)S_H16 * 4;

            // GEMM1: H = relu(RBF @ W1 + b1); warp M=32 x N=32, K=64 (4 k16)
            {
                float acc[2][4][4];
#pragma unroll
                for (int mt = 0; mt < 2; mt++)
#pragma unroll
                    for (int n8 = 0; n8 < 4; n8++)
#pragma unroll
                        for (int q = 0; q < 4; q++) acc[mt][n8][q] = 0.f;
#pragma unroll
                for (int ks = 0; ks < 4; ks++) {
                    uint32_t a0[4], a1[4];
                    ldsm_x4(a0, sR + (uint32_t)((mg1 * 32 + 0) * LDRH + ks * 16) * 2u + aoff_r);
                    ldsm_x4(a1, sR + (uint32_t)((mg1 * 32 + 16) * LDRH + ks * 16) * 2u + aoff_r);
#pragma unroll
                    for (int n8 = 0; n8 < 4; n8++) {
                        mma_f16(acc[0][n8], a0, b1f[ks][n8][0], b1f[ks][n8][1]);
                        mma_f16(acc[1][n8], a1, b1f[ks][n8][0], b1f[ks][n8][1]);
                    }
                }
#pragma unroll
                for (int n8 = 0; n8 < 4; n8++) {
                    int col = ng1 * 32 + n8 * 8 + tig * 2;
                    float2 bz = *(const float2*)(s_b1 + col);
#pragma unroll
                    for (int mt = 0; mt < 2; mt++) {
                        int r0 = mg1 * 32 + mt * 16 + qr;
                        float* a = acc[mt][n8];
                        *(uint32_t*)(s_H16 + (r0 * LDHH + col) * 2) =
                            pack_h2(fmaxf(a[0] + bz.x, 0.f), fmaxf(a[1] + bz.y, 0.f));
                        *(uint32_t*)(s_H16 + ((r0 + 8) * LDHH + col) * 2) =
                            pack_h2(fmaxf(a[2] + bz.x, 0.f), fmaxf(a[3] + bz.y, 0.f));
                    }
                }
            }
            bar_compute();

            // GEMM2: Wt = H @ W2 + b2; warp 2M x 4N, K=128 (8 k16)
            {
                const int mg = wid >> 2;
                const int ng = wid & 3;
                float acc[2][4][4];
#pragma unroll
                for (int mt = 0; mt < 2; mt++)
#pragma unroll
                    for (int n8 = 0; n8 < 4; n8++)
#pragma unroll
                        for (int q = 0; q < 4; q++) acc[mt][n8][q] = 0.f;
#pragma unroll
                for (int ks = 0; ks < 8; ks++) {
                    uint32_t a0[4], a1[4];
                    ldsm_x4(a0, sH_u32 + (uint32_t)((mg * 32 + 0) * LDHH + ks * 16) * 2u + aoff_h);
                    ldsm_x4(a1, sH_u32 + (uint32_t)((mg * 32 + 16) * LDHH + ks * 16) * 2u + aoff_h);
#pragma unroll
                    for (int n8 = 0; n8 < 4; n8++) {
                        uint2 b = w2s[(ks * 16 + ng * 4 + n8) * 32 + lane];
                        mma_f16(acc[0][n8], a0, b.x, b.y);
                        mma_f16(acc[1][n8], a1, b.x, b.y);
                    }
                }
#pragma unroll
                for (int n8 = 0; n8 < 4; n8++) {
                    int col = ng * 32 + n8 * 8 + tig * 2;
                    float2 bz = *(const float2*)(s_b2 + col);
#pragma unroll
                    for (int mt = 0; mt < 2; mt++) {
                        int r0 = mg * 32 + mt * 16 + qr;
                        float* a = acc[mt][n8];
                        *(float2*)(s_out + r0 * LDO + col) =
                            make_float2(a[0] + bz.x, a[1] + bz.y);
                        *(float2*)(s_out + (r0 + 8) * LDO + col) =
                            make_float2(a[2] + bz.x, a[3] + bz.y);
                    }
                }
            }
        } else {
            // ================= SCATTER GROUP =================
            const int sw = wid - 8;
            const int tids = tid - 256;
            int nx = tile + step;
            bool pf = (nx < NT64);
            if (pf) {
                prefetch_stage(sbase, rbf, nx, tids);
                cp_commit();
            }
            if (i > 0) {
                const int p = tile - step;
                float* s_outp = sm + (((i - 1) & 1) ? S_OUT1 : S_OUT0);
                const size_t e0 = (size_t)p * TILE64;
                int e8 = sw * 8 + (lane & 7);
                int dstv = eidx[e0 + e8];
                int srcv = eidx[(size_t)N_EDGES + e0 + e8];
#pragma unroll
                for (int half = 0; half < 2; half++) {
                    float4 hv[4];
                    int d4[4];
#pragma unroll
                    for (int u = 0; u < 4; u++) {
                        int u8 = half * 4 + u;
                        int srow = __shfl_sync(0xffffffffu, srcv, u8);
                        d4[u]    = __shfl_sync(0xffffffffu, dstv, u8);
                        hv[u] = h4_to_f4(*(const uint2*)(h16 + (size_t)srow * OUT_CH + lane * 4));
                    }
#pragma unroll
                    for (int u = 0; u < 4; u++) {
                        int e = sw * 8 + half * 4 + u;
                        float4 wv = *(const float4*)(s_outp + e * LDO + lane * 4);
                        red_add_v4(out + (size_t)d4[u] * OUT_CH + lane * 4,
                                   make_float4(hv[u].x * wv.x, hv[u].y * wv.y,
                                               hv[u].z * wv.z, hv[u].w * wv.w));
                    }
                }
            }
            if (pf) {
                cp_wait0();
                convert_stage(sm, sbase, (i + 1) & 1, tids);
            }
        }
        __syncthreads();
    }

    // ---- drain: scatter the last tile this CTA computed ----
    if (i > 0 && wid >= 8) {
        const int sw = wid - 8;
        const int p = tile - step;
        float* s_outp = sm + (((i - 1) & 1) ? S_OUT1 : S_OUT0);
        const size_t e0 = (size_t)p * TILE64;
        int e8 = sw * 8 + (lane & 7);
        int dstv = eidx[e0 + e8];
        int srcv = eidx[(size_t)N_EDGES + e0 + e8];
#pragma unroll
        for (int half = 0; half < 2; half++) {
            float4 hv[4];
            int d4[4];
#pragma unroll
            for (int u = 0; u < 4; u++) {
                int u8 = half * 4 + u;
                int srow = __shfl_sync(0xffffffffu, srcv, u8);
                d4[u]    = __shfl_sync(0xffffffffu, dstv, u8);
                hv[u] = h4_to_f4(*(const uint2*)(h16 + (size_t)srow * OUT_CH + lane * 4));
            }
#pragma unroll
            for (int u = 0; u < 4; u++) {
                int e = sw * 8 + half * 4 + u;
                float4 wv = *(const float4*)(s_outp + e * LDO + lane * 4);
                red_add_v4(out + (size_t)d4[u] * OUT_CH + lane * 4,
                           make_float4(hv[u].x * wv.x, hv[u].y * wv.y,
                                       hv[u].z * wv.z, hv[u].w * wv.w));
            }
        }
    }
}

// ---------------------------------------------------------------------------
extern "C" void kernel_launch(void* const* d_in, const int* in_sizes, int n_in,
                              void* d_out, int out_size) {
    const float* x    = (const float*)d_in[0];
    const int*   eidx = (const int*)d_in[1];
    const float* rbf  = (const float*)d_in[2];
    const float* W1   = (const float*)d_in[3];
    const float* b1   = (const float*)d_in[4];
    const float* W2   = (const float*)d_in[5];
    const float* b2   = (const float*)d_in[6];
    const float* Wl   = (const float*)d_in[7];
    const float* bl   = (const float*)d_in[8];
    float* out = (float*)d_out;

    static __half* h_ptr = nullptr;
    static int n_sms = 0;
    if (!h_ptr) {
        cudaGetSymbolAddress((void**)&h_ptr, g_h16);
        cudaDeviceGetAttribute(&n_sms, cudaDevAttrMultiProcessorCount, 0);
        cudaFuncSetAttribute(edge_kernel_f16,
                             cudaFuncAttributeMaxDynamicSharedMemorySize, SM_BYTES);
        cudaFuncSetAttribute(node_linear_f16,
                             cudaFuncAttributeMaxDynamicSharedMemorySize, NL_SMEM_BYTES);
    }

    cudaMemsetAsync(d_out, 0, (size_t)N_NODES * OUT_CH * sizeof(float), 0);
    node_linear_f16<<<(N_NODES + 127) / 128, 256, NL_SMEM_BYTES>>>(x, Wl, bl, h_ptr);
    edge_kernel_f16<<<n_sms, 512, SM_BYTES>>>(rbf, eidx, W1, b1, W2, b2,
                                              h_ptr, out, n_sms);
}